// round 11
// baseline (speedup 1.0000x reference)
#include <cuda_runtime.h>
#include <cuda_bf16.h>
#include <cuda_fp16.h>
#include <cstdint>

// Problem constants: B=2, H=16, S=2048, D=64
#define BB 2
#define HH 16
#define SEQ 2048
#define DIM 64
#define BH (BB*HH)

// Scratch: V transposed, fp16  vT[bh][d][k]  (8.4 MB)
__device__ __half g_vT_f16[(size_t)BH * DIM * SEQ];

// ---------------------------------------------------------------------------
// Helpers
// ---------------------------------------------------------------------------
__device__ __forceinline__ uint32_t smem_u32(const void* p) {
    uint32_t a;
    asm("{ .reg .u64 t; cvta.to.shared.u64 t, %1; cvt.u32.u64 %0, t; }" : "=r"(a) : "l"(p));
    return a;
}
#define SW128(x) ((uint32_t)(x) ^ ((((uint32_t)(x)) >> 3) & 0x70))
// swizzle for 64-byte rows: XOR 16B-unit bits [5:4] with row bits (off bits [8:7])
#define SW64X(x) ((uint32_t)(x) ^ ((((uint32_t)(x)) >> 3) & 0x30))

__device__ __forceinline__ void ldmx4(uint32_t* r, uint32_t addr) {
    asm volatile("ldmatrix.sync.aligned.m8n8.x4.shared.b16 {%0,%1,%2,%3}, [%4];"
                 : "=r"(r[0]), "=r"(r[1]), "=r"(r[2]), "=r"(r[3]) : "r"(addr));
}
__device__ __forceinline__ void mma16816bf(float* c, const uint32_t* a, const uint32_t* b) {
    asm volatile("mma.sync.aligned.m16n8k16.row.col.f32.bf16.bf16.f32 "
                 "{%0,%1,%2,%3}, {%4,%5,%6,%7}, {%8,%9}, {%0,%1,%2,%3};"
                 : "+f"(c[0]), "+f"(c[1]), "+f"(c[2]), "+f"(c[3])
                 : "r"(a[0]), "r"(a[1]), "r"(a[2]), "r"(a[3]), "r"(b[0]), "r"(b[1]));
}
__device__ __forceinline__ void mma16816h(float* c, const uint32_t* a, const uint32_t* b) {
    asm volatile("mma.sync.aligned.m16n8k16.row.col.f32.f16.f16.f32 "
                 "{%0,%1,%2,%3}, {%4,%5,%6,%7}, {%8,%9}, {%0,%1,%2,%3};"
                 : "+f"(c[0]), "+f"(c[1]), "+f"(c[2]), "+f"(c[3])
                 : "r"(a[0]), "r"(a[1]), "r"(a[2]), "r"(a[3]), "r"(b[0]), "r"(b[1]));
}

// fp32 -> bf16 hi/lo split of 8 consecutive floats (qk path)
__device__ __forceinline__ void split8(const float* p, uint4& hi, uint4& lo) {
    float4 a = *(const float4*)p;
    float4 b = *(const float4*)(p + 4);
    float x[8] = {a.x, a.y, a.z, a.w, b.x, b.y, b.z, b.w};
    __nv_bfloat162* hp = (__nv_bfloat162*)&hi;
    __nv_bfloat162* lp = (__nv_bfloat162*)&lo;
#pragma unroll
    for (int i = 0; i < 4; i++) {
        __nv_bfloat16 h0 = __float2bfloat16(x[2*i]);
        __nv_bfloat16 h1 = __float2bfloat16(x[2*i+1]);
        float r0 = x[2*i]   - __bfloat162float(h0);
        float r1 = x[2*i+1] - __bfloat162float(h1);
        hp[i] = __halves2bfloat162(h0, h1);
        lp[i] = __floats2bfloat162_rn(r0, r1);
    }
}

// ---------------------------------------------------------------------------
// Kernel 0: V transpose + fp16 convert  v[bh][k][d] -> vT[bh][d][k]
// ---------------------------------------------------------------------------
__global__ __launch_bounds__(256) void vsplit_kernel(const float* __restrict__ v) {
    __shared__ float s[32][33];
    int k0 = blockIdx.x * 32, d0 = blockIdx.y * 32, bh = blockIdx.z;
    const float* vb = v + (size_t)bh * SEQ * DIM;
    int t = threadIdx.x;
#pragma unroll
    for (int i = 0; i < 4; i++) {
        int e = t + i * 256;
        int kk = e >> 5, dd = e & 31;
        s[kk][dd] = vb[(size_t)(k0 + kk) * DIM + d0 + dd];
    }
    __syncthreads();
#pragma unroll
    for (int i = 0; i < 4; i++) {
        int e = t + i * 256;
        int dd = e >> 5, kk = e & 31;
        size_t o = ((size_t)bh * DIM + d0 + dd) * SEQ + k0 + kk;
        g_vT_f16[o] = __float2half(s[kk][dd]);
    }
}

// ---------------------------------------------------------------------------
// Kernel 1: scores = (Q . K^T)/8 via mma.sync bf16 hi/lo split. (unchanged)
// ---------------------------------------------------------------------------
#define QK_QHI 0u
#define QK_QLO 16384u
#define QK_KHI 32768u
#define QK_KLO 49152u
#define QK_SMEM 65536

__global__ __launch_bounds__(256) void qk_mma_kernel(
    const float* __restrict__ q, const float* __restrict__ k,
    float* __restrict__ attn)
{
    extern __shared__ char smem[];
    uint32_t sbase = smem_u32(smem);
    const int tid = threadIdx.x;
    const int wid = tid >> 5;
    const int lane = tid & 31;
    const int wr = wid >> 2;
    const int wc = wid & 3;

    const int bh = blockIdx.z;
    const int q0 = blockIdx.y * 128;
    const int k0 = blockIdx.x * 128;
    const float* qb = q + ((size_t)bh * SEQ + q0) * DIM;
    const float* kb = k + ((size_t)bh * SEQ + k0) * DIM;

    for (int t = tid; t < 1024; t += 256) {
        int row = t >> 3, c0 = (t & 7) << 3;
        uint32_t off = SW128(row * 128 + c0 * 2);
        uint4 hi, lo;
        split8(qb + (size_t)row * DIM + c0, hi, lo);
        *(uint4*)(smem + QK_QHI + off) = hi;
        *(uint4*)(smem + QK_QLO + off) = lo;
        split8(kb + (size_t)row * DIM + c0, hi, lo);
        *(uint4*)(smem + QK_KHI + off) = hi;
        *(uint4*)(smem + QK_KLO + off) = lo;
    }
    __syncthreads();

    float acc[4][4][4];
#pragma unroll
    for (int m = 0; m < 4; m++)
#pragma unroll
        for (int n = 0; n < 4; n++)
#pragma unroll
            for (int i = 0; i < 4; i++) acc[m][n][i] = 0.0f;

    const int a_row = wr * 64 + (lane & 15);
    const int a_cb  = (lane >> 4) << 4;
    const int b_row = wc * 32 + ((lane >> 4) << 3) + (lane & 7);
    const int b_cb  = ((lane >> 3) & 1) << 4;

#pragma unroll
    for (int kc = 0; kc < 4; kc++) {
        const int kb16 = kc * 32;
        uint32_t Ahi[4][4], Alo[4][4];
#pragma unroll
        for (int m = 0; m < 4; m++) {
            uint32_t off = SW128((a_row + m * 16) * 128 + kb16 + a_cb);
            ldmx4(Ahi[m], sbase + QK_QHI + off);
            ldmx4(Alo[m], sbase + QK_QLO + off);
        }
        uint32_t Bhi[2][4], Blo[2][4];
#pragma unroll
        for (int p = 0; p < 2; p++) {
            uint32_t off = SW128((b_row + p * 16) * 128 + kb16 + b_cb);
            ldmx4(Bhi[p], sbase + QK_KHI + off);
            ldmx4(Blo[p], sbase + QK_KLO + off);
        }
#pragma unroll
        for (int m = 0; m < 4; m++)
#pragma unroll
            for (int n = 0; n < 4; n++) {
                const uint32_t* bh2 = &Bhi[n >> 1][(n & 1) * 2];
                const uint32_t* bl2 = &Blo[n >> 1][(n & 1) * 2];
                mma16816bf(acc[m][n], Ahi[m], bh2);
                mma16816bf(acc[m][n], Ahi[m], bl2);
                mma16816bf(acc[m][n], Alo[m], bh2);
            }
    }

    float* ab = attn + ((size_t)bh * SEQ + q0) * SEQ + k0;
    const int er = (lane >> 2);
    const int ec = (lane & 3) * 2;
#pragma unroll
    for (int m = 0; m < 4; m++) {
        int row = wr * 64 + m * 16 + er;
#pragma unroll
        for (int n = 0; n < 4; n++) {
            int col = wc * 32 + n * 8 + ec;
            float2 v0 = { acc[m][n][0] * 0.125f, acc[m][n][1] * 0.125f };
            float2 v1 = { acc[m][n][2] * 0.125f, acc[m][n][3] * 0.125f };
            *(float2*)(ab + (size_t)row * SEQ + col) = v0;
            *(float2*)(ab + (size_t)(row + 8) * SEQ + col) = v1;
        }
    }
}

// ---------------------------------------------------------------------------
// Kernel 2 (FUSED softmax + AV, pipelined): CTA = (b, 16 q-rows, all 16 heads)
// 512 threads = 16 warps; warp w = head w, and handles softmax q-row w.
// Loop over 64 k-chunks of 32, software-pipelined:
//   phase A: commit prefetched V regs -> smem; exp/normalize prefetched
//            scores; write fp32 attn (global) + fp16 A planes (smem)
//   sync
//   phase B: issue next chunk's score + V loads into regs; MMA current chunk
//   sync
// smem: V planes 16 x (64 rows x 64B, SW64) = 64KB; A planes 16 x (16 x 64B)
//       = 16KB. Total 80KB. SW64 swizzle keeps ldmatrix conflict-free.
// ---------------------------------------------------------------------------
#define FQT 16
#define FK2 32
#define FV_STRIDE 4096u        // per-head V plane bytes (64 x 64B)
#define FA_BASE   65536u
#define FA_STRIDE 1024u        // per-head A plane bytes (16 x 64B)
#define FAV_SMEM  81920

__global__ __launch_bounds__(512) void softmax_av_fused_kernel(
    float* __restrict__ attn, float* __restrict__ out)
{
    extern __shared__ char smem[];
    uint32_t sbase = smem_u32(smem);
    const int tid = threadIdx.x;
    const int wid = tid >> 5;              // head (and softmax q-row)
    const int lane = tid & 31;

    const int bq = blockIdx.x;             // 0..255
    const int b  = bq >> 7;
    const int q0 = (bq & 127) * FQT;

    const size_t plane = (size_t)SEQ * SEQ;
    const __half* vt = g_vT_f16 + (size_t)(b * HH + wid) * DIM * SEQ;
    float* ab = attn + (size_t)b * HH * plane;

    // softmax mapping: warp w handles q-row (q0 + w), lane = k offset
    const size_t srow = (size_t)(q0 + wid) * SEQ + lane;

    // V staging mapping: lane covers (d = idx>>2, 16B-unit j = idx&3)
    float acc[8][4];
#pragma unroll
    for (int n = 0; n < 8; n++)
#pragma unroll
        for (int i = 0; i < 4; i++) acc[n][i] = 0.0f;

    const int a_row = lane & 15;
    const int a_cb  = (lane >> 4) << 4;
    const int b_row = ((lane >> 4) << 3) + (lane & 7);
    const int b_cb  = ((lane >> 3) & 1) << 4;
    const uint32_t Vp = sbase + wid * FV_STRIDE;
    const uint32_t Ap = sbase + FA_BASE + wid * FA_STRIDE;

    float sreg[HH];
    uint4 vreg[8];

    // ---- prologue: prefetch chunk 0
#pragma unroll
    for (int hh = 0; hh < HH; hh++)
        sreg[hh] = ab[hh * plane + srow];
#pragma unroll
    for (int i = 0; i < 8; i++) {
        int idx = lane + i * 32;
        int d = idx >> 2, j = idx & 3;
        vreg[i] = *(const uint4*)(vt + (size_t)d * SEQ + j * 8);
    }

    for (int ic = 0; ic < SEQ / FK2; ic++) {
        const int kc0 = ic * FK2;

        // ---- phase A: commit V regs to smem
#pragma unroll
        for (int i = 0; i < 8; i++) {
            int idx = lane + i * 32;
            int d = idx >> 2, j = idx & 3;
            *(uint4*)(smem + wid * FV_STRIDE + SW64X(d * 64 + j * 16)) = vreg[i];
        }
        // softmax from prefetched scores
        {
            float s = 0.0f;
#pragma unroll
            for (int hh = 0; hh < HH; hh++) {
                sreg[hh] = __expf(sreg[hh]);
                s += sreg[hh];
            }
            const float inv = 1.0f / s;
            const size_t base = srow + kc0;
            const uint32_t aoff = SW64X((uint32_t)(wid * 64 + lane * 2));
#pragma unroll
            for (int hh = 0; hh < HH; hh++) {
                float a = sreg[hh] * inv;
                ab[hh * plane + base] = a;
                *(__half*)(smem + FA_BASE + hh * FA_STRIDE + aoff) = __float2half(a);
            }
        }
        __syncthreads();

        // ---- phase B: prefetch next chunk, then MMA current
        if (ic < SEQ / FK2 - 1) {
            const size_t nbase = srow + kc0 + FK2;
#pragma unroll
            for (int hh = 0; hh < HH; hh++)
                sreg[hh] = ab[hh * plane + nbase];
#pragma unroll
            for (int i = 0; i < 8; i++) {
                int idx = lane + i * 32;
                int d = idx >> 2, j = idx & 3;
                vreg[i] = *(const uint4*)(vt + (size_t)d * SEQ + kc0 + FK2 + j * 8);
            }
        }
#pragma unroll
        for (int kc = 0; kc < 2; kc++) {
            uint32_t Ah[4];
            ldmx4(Ah, Ap + SW64X(a_row * 64 + kc * 32 + a_cb));
            uint32_t Bh[4][4];
#pragma unroll
            for (int p = 0; p < 4; p++)
                ldmx4(Bh[p], Vp + SW64X((p * 16 + b_row) * 64 + kc * 32 + b_cb));
#pragma unroll
            for (int n = 0; n < 8; n++)
                mma16816h(acc[n], Ah, &Bh[n >> 1][(n & 1) * 2]);
        }
        __syncthreads();
    }

    // ---- epilogue: warp writes its head's out block (16q x 64d)
    float* ob = out + ((size_t)(b * HH + wid) * SEQ + q0) * DIM;
    const int er = lane >> 2;
    const int ec = (lane & 3) * 2;
#pragma unroll
    for (int n = 0; n < 8; n++) {
        int col = n * 8 + ec;
        float2 v0 = { acc[n][0], acc[n][1] };
        float2 v1 = { acc[n][2], acc[n][3] };
        *(float2*)(ob + (size_t)er * DIM + col) = v0;
        *(float2*)(ob + (size_t)(er + 8) * DIM + col) = v1;
    }
}

// ---------------------------------------------------------------------------
// Launch: d_out = [ out (B*H*S*D) | attn (B*H*S*S) ]
// ---------------------------------------------------------------------------
extern "C" void kernel_launch(void* const* d_in, const int* in_sizes, int n_in,
                              void* d_out, int out_size)
{
    const float* q = (const float*)d_in[0];
    const float* k = (const float*)d_in[1];
    const float* v = (const float*)d_in[2];

    float* out  = (float*)d_out;
    float* attn = out + (size_t)BB * HH * SEQ * DIM;

    cudaFuncSetAttribute(qk_mma_kernel,
                         cudaFuncAttributeMaxDynamicSharedMemorySize, QK_SMEM);
    cudaFuncSetAttribute(softmax_av_fused_kernel,
                         cudaFuncAttributeMaxDynamicSharedMemorySize, FAV_SMEM);

    // 0) V transpose + fp16 convert
    {
        dim3 grid(SEQ / 32, DIM / 32, BH);
        vsplit_kernel<<<grid, 256>>>(v);
    }
    // 1) raw scores -> attn region
    {
        dim3 grid(SEQ / 128, SEQ / 128, BH);
        qk_mma_kernel<<<grid, 256, QK_SMEM>>>(q, k, attn);
    }
    // 2) fused: softmax over heads (in-place on attn) + out = attn @ V
    {
        dim3 grid((SEQ / FQT) * BB);
        softmax_av_fused_kernel<<<grid, 512, FAV_SMEM>>>(attn, out);
    }
}

// round 14
// speedup vs baseline: 1.1017x; 1.1017x over previous
#include <cuda_runtime.h>
#include <cuda_bf16.h>
#include <cuda_fp16.h>
#include <cstdint>

// Problem constants: B=2, H=16, S=2048, D=64
#define BB 2
#define HH 16
#define SEQ 2048
#define DIM 64
#define BH (BB*HH)

// Scratch: V transposed, fp16  vT[bh][d][k]  (8.4 MB)
__device__ __half g_vT_f16[(size_t)BH * DIM * SEQ];

// ---------------------------------------------------------------------------
// Helpers
// ---------------------------------------------------------------------------
__device__ __forceinline__ uint32_t smem_u32(const void* p) {
    uint32_t a;
    asm("{ .reg .u64 t; cvta.to.shared.u64 t, %1; cvt.u32.u64 %0, t; }" : "=r"(a) : "l"(p));
    return a;
}
#define SW128(x) ((uint32_t)(x) ^ ((((uint32_t)(x)) >> 3) & 0x70))
// swizzle for 64-byte rows
#define SW64X(x) ((uint32_t)(x) ^ ((((uint32_t)(x)) >> 3) & 0x30))

#define CP_ASYNC16(dst, src) \
    asm volatile("cp.async.ca.shared.global [%0], [%1], 16;" :: "r"(dst), "l"(src))
#define CP_COMMIT() asm volatile("cp.async.commit_group;" ::: "memory")
#define CP_WAIT0()  asm volatile("cp.async.wait_group 0;" ::: "memory")

__device__ __forceinline__ void ldmx4(uint32_t* r, uint32_t addr) {
    asm volatile("ldmatrix.sync.aligned.m8n8.x4.shared.b16 {%0,%1,%2,%3}, [%4];"
                 : "=r"(r[0]), "=r"(r[1]), "=r"(r[2]), "=r"(r[3]) : "r"(addr));
}
__device__ __forceinline__ void mma16816bf(float* c, const uint32_t* a, const uint32_t* b) {
    asm volatile("mma.sync.aligned.m16n8k16.row.col.f32.bf16.bf16.f32 "
                 "{%0,%1,%2,%3}, {%4,%5,%6,%7}, {%8,%9}, {%0,%1,%2,%3};"
                 : "+f"(c[0]), "+f"(c[1]), "+f"(c[2]), "+f"(c[3])
                 : "r"(a[0]), "r"(a[1]), "r"(a[2]), "r"(a[3]), "r"(b[0]), "r"(b[1]));
}
__device__ __forceinline__ void mma16816h(float* c, const uint32_t* a, const uint32_t* b) {
    asm volatile("mma.sync.aligned.m16n8k16.row.col.f32.f16.f16.f32 "
                 "{%0,%1,%2,%3}, {%4,%5,%6,%7}, {%8,%9}, {%0,%1,%2,%3};"
                 : "+f"(c[0]), "+f"(c[1]), "+f"(c[2]), "+f"(c[3])
                 : "r"(a[0]), "r"(a[1]), "r"(a[2]), "r"(a[3]), "r"(b[0]), "r"(b[1]));
}

// fp32 -> bf16 hi/lo split of 8 consecutive floats (qk path)
__device__ __forceinline__ void split8(const float* p, uint4& hi, uint4& lo) {
    float4 a = *(const float4*)p;
    float4 b = *(const float4*)(p + 4);
    float x[8] = {a.x, a.y, a.z, a.w, b.x, b.y, b.z, b.w};
    __nv_bfloat162* hp = (__nv_bfloat162*)&hi;
    __nv_bfloat162* lp = (__nv_bfloat162*)&lo;
#pragma unroll
    for (int i = 0; i < 4; i++) {
        __nv_bfloat16 h0 = __float2bfloat16(x[2*i]);
        __nv_bfloat16 h1 = __float2bfloat16(x[2*i+1]);
        float r0 = x[2*i]   - __bfloat162float(h0);
        float r1 = x[2*i+1] - __bfloat162float(h1);
        hp[i] = __halves2bfloat162(h0, h1);
        lp[i] = __floats2bfloat162_rn(r0, r1);
    }
}

// ---------------------------------------------------------------------------
// Kernel 0: V transpose + fp16 convert  v[bh][k][d] -> vT[bh][d][k]
// ---------------------------------------------------------------------------
__global__ __launch_bounds__(256) void vsplit_kernel(const float* __restrict__ v) {
    __shared__ float s[32][33];
    int k0 = blockIdx.x * 32, d0 = blockIdx.y * 32, bh = blockIdx.z;
    const float* vb = v + (size_t)bh * SEQ * DIM;
    int t = threadIdx.x;
#pragma unroll
    for (int i = 0; i < 4; i++) {
        int e = t + i * 256;
        int kk = e >> 5, dd = e & 31;
        s[kk][dd] = vb[(size_t)(k0 + kk) * DIM + d0 + dd];
    }
    __syncthreads();
#pragma unroll
    for (int i = 0; i < 4; i++) {
        int e = t + i * 256;
        int dd = e >> 5, kk = e & 31;
        size_t o = ((size_t)bh * DIM + d0 + dd) * SEQ + k0 + kk;
        g_vT_f16[o] = __float2half(s[kk][dd]);
    }
}

// ---------------------------------------------------------------------------
// Kernel 1: scores = (Q . K^T)/8 via mma.sync bf16 hi/lo split. (unchanged)
// ---------------------------------------------------------------------------
#define QK_QHI 0u
#define QK_QLO 16384u
#define QK_KHI 32768u
#define QK_KLO 49152u
#define QK_SMEM 65536

__global__ __launch_bounds__(256) void qk_mma_kernel(
    const float* __restrict__ q, const float* __restrict__ k,
    float* __restrict__ attn)
{
    extern __shared__ char smem[];
    uint32_t sbase = smem_u32(smem);
    const int tid = threadIdx.x;
    const int wid = tid >> 5;
    const int lane = tid & 31;
    const int wr = wid >> 2;
    const int wc = wid & 3;

    const int bh = blockIdx.z;
    const int q0 = blockIdx.y * 128;
    const int k0 = blockIdx.x * 128;
    const float* qb = q + ((size_t)bh * SEQ + q0) * DIM;
    const float* kb = k + ((size_t)bh * SEQ + k0) * DIM;

    for (int t = tid; t < 1024; t += 256) {
        int row = t >> 3, c0 = (t & 7) << 3;
        uint32_t off = SW128(row * 128 + c0 * 2);
        uint4 hi, lo;
        split8(qb + (size_t)row * DIM + c0, hi, lo);
        *(uint4*)(smem + QK_QHI + off) = hi;
        *(uint4*)(smem + QK_QLO + off) = lo;
        split8(kb + (size_t)row * DIM + c0, hi, lo);
        *(uint4*)(smem + QK_KHI + off) = hi;
        *(uint4*)(smem + QK_KLO + off) = lo;
    }
    __syncthreads();

    float acc[4][4][4];
#pragma unroll
    for (int m = 0; m < 4; m++)
#pragma unroll
        for (int n = 0; n < 4; n++)
#pragma unroll
            for (int i = 0; i < 4; i++) acc[m][n][i] = 0.0f;

    const int a_row = wr * 64 + (lane & 15);
    const int a_cb  = (lane >> 4) << 4;
    const int b_row = wc * 32 + ((lane >> 4) << 3) + (lane & 7);
    const int b_cb  = ((lane >> 3) & 1) << 4;

#pragma unroll
    for (int kc = 0; kc < 4; kc++) {
        const int kb16 = kc * 32;
        uint32_t Ahi[4][4], Alo[4][4];
#pragma unroll
        for (int m = 0; m < 4; m++) {
            uint32_t off = SW128((a_row + m * 16) * 128 + kb16 + a_cb);
            ldmx4(Ahi[m], sbase + QK_QHI + off);
            ldmx4(Alo[m], sbase + QK_QLO + off);
        }
        uint32_t Bhi[2][4], Blo[2][4];
#pragma unroll
        for (int p = 0; p < 2; p++) {
            uint32_t off = SW128((b_row + p * 16) * 128 + kb16 + b_cb);
            ldmx4(Bhi[p], sbase + QK_KHI + off);
            ldmx4(Blo[p], sbase + QK_KLO + off);
        }
#pragma unroll
        for (int m = 0; m < 4; m++)
#pragma unroll
            for (int n = 0; n < 4; n++) {
                const uint32_t* bh2 = &Bhi[n >> 1][(n & 1) * 2];
                const uint32_t* bl2 = &Blo[n >> 1][(n & 1) * 2];
                mma16816bf(acc[m][n], Ahi[m], bh2);
                mma16816bf(acc[m][n], Ahi[m], bl2);
                mma16816bf(acc[m][n], Alo[m], bh2);
            }
    }

    float* ab = attn + ((size_t)bh * SEQ + q0) * SEQ + k0;
    const int er = (lane >> 2);
    const int ec = (lane & 3) * 2;
#pragma unroll
    for (int m = 0; m < 4; m++) {
        int row = wr * 64 + m * 16 + er;
#pragma unroll
        for (int n = 0; n < 4; n++) {
            int col = wc * 32 + n * 8 + ec;
            float2 v0 = { acc[m][n][0] * 0.125f, acc[m][n][1] * 0.125f };
            float2 v1 = { acc[m][n][2] * 0.125f, acc[m][n][3] * 0.125f };
            *(float2*)(ab + (size_t)row * SEQ + col) = v0;
            *(float2*)(ab + (size_t)(row + 8) * SEQ + col) = v1;
        }
    }
}

// ---------------------------------------------------------------------------
// Kernel 2 (FUSED softmax + AV, pipelined, FQT=32): CTA = (b, 32 q, 16 heads)
// 512 threads = 16 warps; warp w = head w.
// Per 32-k chunk: phase A waits cp.async V, softmaxes prefetched scores,
// writes fp32 attn + fp16 A planes; phase B issues next chunk's cp.async V
// and score LDGs, then MMAs the current chunk.
// smem: V double buffer 2 x 16 x (64 x 64B SW64) = 128KB at 0/64KB;
//       A planes 16 x (32 x 64B SW64) = 32KB at 128KB. Total 160KB.
// ---------------------------------------------------------------------------
#define FV_STRIDE 4096u
#define FV_BUF1   65536u
#define FA_BASE   131072u
#define FA_STRIDE 2048u
#define FAV_SMEM  163840

__global__ __launch_bounds__(512) void softmax_av_fused_kernel(
    float* __restrict__ attn, float* __restrict__ out)
{
    extern __shared__ char smem[];
    uint32_t sbase = smem_u32(smem);
    const int tid = threadIdx.x;
    const int wid = tid >> 5;              // head
    const int lane = tid & 31;
    const int b  = blockIdx.y;
    const int q0 = blockIdx.x * 32;

    const size_t plane = (size_t)SEQ * SEQ;
    const __half* vt = g_vT_f16 + (size_t)(b * HH + wid) * DIM * SEQ;
    float* ab = attn + (size_t)b * HH * plane;

    // softmax mapping: thread handles (q = q0+sq, k = sk..sk+1)
    const int sq = tid >> 4;               // 0..31
    const int sk = (lane & 15) * 2;        // 0..30
    const size_t qrow = (size_t)(q0 + sq) * SEQ + sk;

    float acc[2][8][4];
#pragma unroll
    for (int m = 0; m < 2; m++)
#pragma unroll
        for (int n = 0; n < 8; n++)
#pragma unroll
            for (int i = 0; i < 4; i++) acc[m][n][i] = 0.0f;

    const int a_row = lane & 15;
    const int a_cb  = (lane >> 4) << 4;
    const int b_row = ((lane >> 4) << 3) + (lane & 7);
    const int b_cb  = ((lane >> 3) & 1) << 4;
    const uint32_t Ap = sbase + FA_BASE + wid * FA_STRIDE;
    const uint32_t aoff = SW64X((uint32_t)(sq * 64 + sk * 2));

    float ex[HH][2];

    // ---- prologue: prefetch scores chunk 0 + cp.async V chunk 0 into buf 0
#pragma unroll
    for (int hh = 0; hh < HH; hh++) {
        float2 v = *(const float2*)(ab + hh * plane + qrow);
        ex[hh][0] = v.x; ex[hh][1] = v.y;
    }
#pragma unroll
    for (int i = 0; i < 8; i++) {
        int idx = lane + i * 32;
        int d = idx >> 2, j = idx & 3;
        CP_ASYNC16(sbase + wid * FV_STRIDE + SW64X(d * 64 + j * 16),
                   vt + (size_t)d * SEQ + j * 8);
    }
    CP_COMMIT();

    for (int ic = 0; ic < SEQ / 32; ic++) {
        const int kc0 = ic * 32;
        const uint32_t vbuf = (ic & 1) ? FV_BUF1 : 0u;

        // ---- phase A: V chunk ready; softmax prefetched scores
        CP_WAIT0();
        __syncthreads();
        {
            float s0 = 0.0f, s1 = 0.0f;
#pragma unroll
            for (int hh = 0; hh < HH; hh++) {
                ex[hh][0] = __expf(ex[hh][0]);
                ex[hh][1] = __expf(ex[hh][1]);
                s0 += ex[hh][0];
                s1 += ex[hh][1];
            }
            const float i0 = 1.0f / s0, i1 = 1.0f / s1;
            const size_t base = qrow + kc0;
#pragma unroll
            for (int hh = 0; hh < HH; hh++) {
                float a0 = ex[hh][0] * i0;
                float a1 = ex[hh][1] * i1;
                float2 w = { a0, a1 };
                *(float2*)(ab + hh * plane + base) = w;
                *(__half2*)(smem + FA_BASE + hh * FA_STRIDE + aoff) =
                    __floats2half2_rn(a0, a1);
            }
        }
        __syncthreads();

        // ---- phase B: prefetch next chunk (scores + V), then MMA current
        if (ic < SEQ / 32 - 1) {
            const int nk = kc0 + 32;
#pragma unroll
            for (int hh = 0; hh < HH; hh++) {
                float2 v = *(const float2*)(ab + hh * plane + qrow + nk);
                ex[hh][0] = v.x; ex[hh][1] = v.y;
            }
            const uint32_t nbuf = ((ic + 1) & 1) ? FV_BUF1 : 0u;
#pragma unroll
            for (int i = 0; i < 8; i++) {
                int idx = lane + i * 32;
                int d = idx >> 2, j = idx & 3;
                CP_ASYNC16(sbase + nbuf + wid * FV_STRIDE + SW64X(d * 64 + j * 16),
                           vt + (size_t)d * SEQ + nk + j * 8);
            }
            CP_COMMIT();
        }
        {
            const uint32_t Vp = sbase + vbuf + wid * FV_STRIDE;
#pragma unroll
            for (int kc = 0; kc < 2; kc++) {
                uint32_t Ah[2][4];
#pragma unroll
                for (int m = 0; m < 2; m++)
                    ldmx4(Ah[m], Ap + SW64X((m * 16 + a_row) * 64 + kc * 32 + a_cb));
                uint32_t Bh[4][4];
#pragma unroll
                for (int p = 0; p < 4; p++)
                    ldmx4(Bh[p], Vp + SW64X((p * 16 + b_row) * 64 + kc * 32 + b_cb));
#pragma unroll
                for (int m = 0; m < 2; m++)
#pragma unroll
                    for (int n = 0; n < 8; n++)
                        mma16816h(acc[m][n], Ah[m], &Bh[n >> 1][(n & 1) * 2]);
            }
        }
        __syncthreads();
    }

    // ---- epilogue: warp writes its head's out block (32q x 64d)
    float* ob = out + ((size_t)(b * HH + wid) * SEQ + q0) * DIM;
    const int er = lane >> 2;
    const int ec = (lane & 3) * 2;
#pragma unroll
    for (int m = 0; m < 2; m++) {
        int row = m * 16 + er;
#pragma unroll
        for (int n = 0; n < 8; n++) {
            int col = n * 8 + ec;
            float2 v0 = { acc[m][n][0], acc[m][n][1] };
            float2 v1 = { acc[m][n][2], acc[m][n][3] };
            *(float2*)(ob + (size_t)row * DIM + col) = v0;
            *(float2*)(ob + (size_t)(row + 8) * DIM + col) = v1;
        }
    }
}

// ---------------------------------------------------------------------------
// Launch: d_out = [ out (B*H*S*D) | attn (B*H*S*S) ]
// ---------------------------------------------------------------------------
extern "C" void kernel_launch(void* const* d_in, const int* in_sizes, int n_in,
                              void* d_out, int out_size)
{
    const float* q = (const float*)d_in[0];
    const float* k = (const float*)d_in[1];
    const float* v = (const float*)d_in[2];

    float* out  = (float*)d_out;
    float* attn = out + (size_t)BB * HH * SEQ * DIM;

    cudaFuncSetAttribute(qk_mma_kernel,
                         cudaFuncAttributeMaxDynamicSharedMemorySize, QK_SMEM);
    cudaFuncSetAttribute(softmax_av_fused_kernel,
                         cudaFuncAttributeMaxDynamicSharedMemorySize, FAV_SMEM);

    // 0) V transpose + fp16 convert
    {
        dim3 grid(SEQ / 32, DIM / 32, BH);
        vsplit_kernel<<<grid, 256>>>(v);
    }
    // 1) raw scores -> attn region
    {
        dim3 grid(SEQ / 128, SEQ / 128, BH);
        qk_mma_kernel<<<grid, 256, QK_SMEM>>>(q, k, attn);
    }
    // 2) fused: softmax over heads (in-place on attn) + out = attn @ V
    {
        dim3 grid(SEQ / 32, BB);
        softmax_av_fused_kernel<<<grid, 512, FAV_SMEM>>>(attn, out);
    }
}